// round 11
// baseline (speedup 1.0000x reference)
#include <cuda_runtime.h>
#include <cuda_bf16.h>

// KBpA: fused sparse-grid deformation (separable 21x21 gaussian conv) +
// truncated separable RBF kmat @ alphas.  B=16, H=W=128, 32x32 centers.
// 4 pixels/quad, quad split across TWO threads by ey-columns (6+6 of 12).
// TPB=128, 16x16 tiles, 11x12 window.  7 blocks/SM -> single wave (1024<=1036).

#define TPB 128
#define KCC  0.52729242f    // exp(-0.64)

static __device__ __forceinline__ unsigned long long pk2(float lo, float hi) {
    unsigned long long r;
    asm("mov.b64 %0, {%1, %2};" : "=l"(r) : "f"(lo), "f"(hi));
    return r;
}
static __device__ __forceinline__ float2 unpk2(unsigned long long v) {
    float2 r;
    asm("mov.b64 {%0, %1}, %2;" : "=f"(r.x), "=f"(r.y) : "l"(v));
    return r;
}
static __device__ __forceinline__ void fma2(unsigned long long& d,
                                            unsigned long long a,
                                            unsigned long long b) {
    asm("fma.rn.f32x2 %0, %1, %2, %0;" : "+l"(d) : "l"(a), "l"(b));
}
static __device__ __forceinline__ void mul2o(unsigned long long& d,
                                             unsigned long long a,
                                             unsigned long long b) {
    asm("mul.rn.f32x2 %0, %1, %2;" : "=l"(d) : "l"(a), "l"(b));
}
static __device__ __forceinline__ void add2(unsigned long long& d,
                                            unsigned long long a) {
    asm("add.rn.f32x2 %0, %0, %1;" : "+l"(d) : "l"(a));
}
static __device__ __forceinline__ void mul2(unsigned long long& d,
                                            unsigned long long a) {
    asm("mul.rn.f32x2 %0, %0, %1;" : "+l"(d) : "l"(a));
}

__global__ __launch_bounds__(TPB, 7) void rbf_deform_kernel(
    const float* __restrict__ betas,   // (16, 1024, 2)
    const float* __restrict__ alphas,  // (1024,)
    const float* __restrict__ kern,    // (21, 21)  (separable: g g^T)
    float* __restrict__ out)           // (16, 16384)
{
    __shared__ __align__(16) float sA[24 * 32];       // local alphas window
    __shared__ float sB[2][10][12];                   // local betas window
    __shared__ __align__(16) float sT[2][10][16];     // deformation col-pass
    __shared__ float sG[4][8];                        // 1D conv taps per phase
    __shared__ __align__(16) unsigned long long sR[64][4];  // half-1 partials

    const int b  = blockIdx.y;
    const int r0 = (blockIdx.x >> 3) << 4;
    const int c0 = (blockIdx.x & 7)  << 4;
    const int tid = threadIdx.x;

    const int ribase = (r0 >> 2) - 10;   // sA row 0 = alphas row ribase
    const int cjbase = (c0 >> 2) - 12;   // sA col 0 = alphas col cjbase
    const int gibase = (r0 >> 2) - 2;
    const int gjbase = (c0 >> 2) - 2;

    // ---- cooperative fills (zero padding absorbs all boundaries) ----
    for (int idx = tid; idx < 24 * 32; idx += TPB) {
        const int i = ribase + (idx >> 5), j = cjbase + (idx & 31);
        float v = 0.f;
        if ((unsigned)i < 32u && (unsigned)j < 32u) v = alphas[(i << 5) + j];
        sA[idx] = v;
    }
    for (int idx = tid; idx < 100; idx += TPB) {
        const int rl = idx / 10, clc = idx - rl * 10;
        const int gi = gibase + rl, gj = gjbase + clc;
        float v0 = 0.f, v1 = 0.f;
        if ((unsigned)gi < 32u && (unsigned)gj < 32u) {
            const int m = (((b << 5) + gi) << 5) + gj;
            v0 = betas[2 * m];
            v1 = betas[2 * m + 1];
        }
        sB[0][rl][clc] = v0;
        sB[1][rl][clc] = v1;
    }
    if (tid < 24) {
        const int s = tid / 6, k = tid - s * 6;
        const int dc0 = (s == 3) ? 7 : (8 + s);
        const int dc = dc0 - 4 * k;
        // 1D factor: kern[u][10] == exp(-ax_u^2/18)  (kern[10][10] == 1)
        sG[s][k] = (dc >= -10 && dc <= 10) ? kern[(dc + 10) * 21 + 10] : 0.f;
    }
    __syncthreads();

    // ---- deformation column pass: T[ch][gi][c] = sum_l g_c[l] B[gi, gj0(c)+l]
    for (int idx = tid; idx < 160; idx += TPB) {
        const int giloc = idx >> 4, cloc = idx & 15;
        const int c = c0 + cloc;
        const int s = c & 3;
        const int gjl = (c >> 2) - (c0 >> 2) + (s == 3);
        float t0 = 0.f, t1 = 0.f;
#pragma unroll
        for (int l = 0; l < 6; ++l) {
            const float w = sG[s][l];
            t0 = fmaf(w, sB[0][giloc][gjl + l], t0);
            t1 = fmaf(w, sB[1][giloc][gjl + l], t1);
        }
        sT[0][giloc][cloc] = t0;
        sT[1][giloc][cloc] = t1;
    }
    __syncthreads();

    // ---- quad / half assignment ----
    const int q  = tid & 63;          // quad id within tile
    const int h  = tid >> 6;          // 0: ey cols 0-5, 1: ey cols 6-11
    const int rr = r0 + (q >> 2);
    const int cb = c0 + ((q & 3) << 2);
    const int sr = rr & 3;
    const int g0 = (rr >> 2) - (r0 >> 2) + (sr == 3);
    const int cl = cb - c0;

    // deformation row pass (6 taps), 4 pixels at once (duplicated per half)
    float4 d0 = make_float4(0.f, 0.f, 0.f, 0.f), d1 = d0;
#pragma unroll
    for (int k = 0; k < 6; ++k) {
        const float w = sG[sr][k];
        const float4 t0 = *(const float4*)&sT[0][g0 + k][cl];
        const float4 t1 = *(const float4*)&sT[1][g0 + k][cl];
        d0.x = fmaf(w, t0.x, d0.x); d0.y = fmaf(w, t0.y, d0.y);
        d0.z = fmaf(w, t0.z, d0.z); d0.w = fmaf(w, t0.w, d0.w);
        d1.x = fmaf(w, t1.x, d1.x); d1.y = fmaf(w, t1.y, d1.y);
        d1.z = fmaf(w, t1.z, d1.z); d1.w = fmaf(w, t1.w, d1.w);
    }
    const float xs0 = (float)rr - d0.x, xs1 = (float)rr - d0.y;
    const float xs2 = (float)rr - d0.z, xs3 = (float)rr - d0.w;
    const float ys0 = (float)(cb)     - d1.x, ys1 = (float)(cb + 1) - d1.y;
    const float ys2 = (float)(cb + 2) - d1.z, ys3 = (float)(cb + 3) - d1.w;

    const float xav = (xs0 + xs1 + xs2 + xs3) * 0.25f;
    const float yav = (ys0 + ys1 + ys2 + ys3) * 0.25f;
    const int im = __float2int_rn((xav - 2.f) * 0.25f);
    const int jm = __float2int_rn((yav - 2.f) * 0.25f);
    const int j0 = (jm - 5) & ~1;               // 2-aligned 12-col window
    const int i0 = im - 5;                      // 11-row window

    // this half's 6 ey values per pixel (single 5-mul exp-ratio chain)
    unsigned long long eyp[4][3];
    unsigned long long ee2[4], er2[4], acc2[4];
    const unsigned long long kcc2 = pk2(KCC, KCC);
    const float xsv[4] = {xs0, xs1, xs2, xs3};
    const float ysv[4] = {ys0, ys1, ys2, ys3};
    const float ycen = (float)(4 * (j0 + 6 * h) + 2);
    const float xcen = (float)(4 * i0 + 2);
#pragma unroll
    for (int p = 0; p < 4; ++p) {
        const float dy = ysv[p] - ycen;
        float ea = __expf(dy * dy * -0.02f);
        float ra = __expf(0.16f * dy - 0.32f);
        float ev[6];
        ev[0] = ea;
#pragma unroll
        for (int l = 1; l < 6; ++l) { ea *= ra; ra *= KCC; ev[l] = ea; }
        eyp[p][0] = pk2(ev[0], ev[1]);
        eyp[p][1] = pk2(ev[2], ev[3]);
        eyp[p][2] = pk2(ev[4], ev[5]);

        const float dx = xsv[p] - xcen;
        const float e0 = __expf(dx * dx * -0.02f);
        const float r0f = __expf(0.16f * dx - 0.32f);
        ee2[p]  = pk2(e0, e0);
        er2[p]  = pk2(r0f, r0f);
        acc2[p] = 0ull;
    }

    // main: 11 A rows, this half reads its 6 columns (3 LDS.64 per row)
    const float* Arow = &sA[(i0 - ribase) * 32 + (j0 - cjbase) + 6 * h];
#pragma unroll
    for (int k = 0; k < 11; ++k) {
        const unsigned long long* src = (const unsigned long long*)Arow;
        const unsigned long long Ac0 = src[0];
        const unsigned long long Ac1 = src[1];
        const unsigned long long Ac2 = src[2];
#pragma unroll
        for (int p = 0; p < 4; ++p) {
            unsigned long long s2;
            mul2o(s2, Ac0, eyp[p][0]);
            fma2(s2, Ac1, eyp[p][1]);
            fma2(s2, Ac2, eyp[p][2]);
            fma2(acc2[p], s2, ee2[p]);   // acc += half_dot * ex_k (both lanes)
            mul2(ee2[p], er2[p]);
            mul2(er2[p], kcc2);
        }
        Arow += 32;
    }

    // ---- combine halves ----
    if (h == 1) {
#pragma unroll
        for (int p = 0; p < 4; ++p) sR[q][p] = acc2[p];
    }
    __syncthreads();
    if (h == 0) {
        float res[4];
#pragma unroll
        for (int p = 0; p < 4; ++p) {
            add2(acc2[p], sR[q][p]);
            const float2 v = unpk2(acc2[p]);
            res[p] = v.x + v.y;
        }
        *(float4*)&out[(b << 14) + (rr << 7) + cb] =
            make_float4(res[0], res[1], res[2], res[3]);
    }
}

extern "C" void kernel_launch(void* const* d_in, const int* in_sizes, int n_in,
                              void* d_out, int out_size) {
    const float* betas  = (const float*)d_in[0];
    const float* alphas = (const float*)d_in[1];
    const float* kern   = (const float*)d_in[2];
    float* out = (float*)d_out;

    dim3 grid(64, 16);   // 8x8 tiles of 16x16 pixels, 16 batches
    rbf_deform_kernel<<<grid, TPB>>>(betas, alphas, kern, out);
}